// round 1
// baseline (speedup 1.0000x reference)
#include <cuda_runtime.h>
#include <math.h>

#define B   64
#define T   2000
#define E   512
#define D   1024
#define A   256
#define NF  32
#define KW  31
#define PAD 15
#define BT  (B*T)
#define KTOT (E + NF)   // 544 concatenated K

// scratch (static device globals — no allocation allowed)
__device__ float g_loc[BT * NF];    // location features [B,T,NF]
__device__ float g_dproj[B * A];    // decoder projection [B,A]
__device__ float g_energy[BT];      // pre-softmax energies [B,T]

// ---------------------------------------------------------------------------
// zero energy + context (atomics accumulate into both every replay)
__global__ void k_init(float* __restrict__ ctx) {
    int i = blockIdx.x * blockDim.x + threadIdx.x;
    if (i < BT) g_energy[i] = 0.f;
    if (i < B * E) ctx[i] = 0.f;
}

// ---------------------------------------------------------------------------
// dproj[b,a] = decoder_state[b,:] @ W_dec[:,a]
__global__ void k_dproj(const float* __restrict__ dec, const float* __restrict__ Wd) {
    __shared__ float sdec[256];
    int b = blockIdx.x, a = threadIdx.x;
    float acc = 0.f;
    for (int d0 = 0; d0 < D; d0 += 256) {
        __syncthreads();
        sdec[a] = dec[b * D + d0 + a];
        __syncthreads();
#pragma unroll 8
        for (int dd = 0; dd < 256; dd++)
            acc += sdec[dd] * Wd[(d0 + dd) * A + a];
    }
    g_dproj[b * A + a] = acc;
}

// ---------------------------------------------------------------------------
// loc[b,t,f] = sum_k conv_w[f,0,k] * prev[b, t+k-PAD]   ('same' correlation)
#define CT 128
__global__ void k_conv(const float* __restrict__ prev, const float* __restrict__ cw) {
    __shared__ float sp[CT + KW - 1];
    __shared__ float sw[NF * KW];
    int b = blockIdx.y, t0 = blockIdx.x * CT;
    int tid = threadIdx.x;                       // 256 threads
    for (int i = tid; i < NF * KW; i += 256) sw[i] = cw[i];
    for (int i = tid; i < CT + KW - 1; i += 256) {
        int t = t0 + i - PAD;
        sp[i] = (t >= 0 && t < T) ? prev[b * T + t] : 0.f;
    }
    __syncthreads();
    for (int i = tid; i < CT * NF; i += 256) {
        int tl = i / NF, f = i % NF;
        int t = t0 + tl;
        if (t < T) {
            float acc = 0.f;
#pragma unroll
            for (int k = 0; k < KW; k++) acc += sw[f * KW + k] * sp[tl + k];
            g_loc[(b * T + t) * NF + f] = acc;
        }
    }
}

// ---------------------------------------------------------------------------
// Fused energy GEMM:  [BT, 544] x [544, 256], epilogue  e += v . tanh(z + dproj)
// X = [enc | loc] (concatenated K),  W = [W_enc ; W_loc]
#define BM 64
#define BN 64
#define BK 16
__global__ void __launch_bounds__(256) k_gemm(const float* __restrict__ enc,
                                              const float* __restrict__ We,
                                              const float* __restrict__ Wl,
                                              const float* __restrict__ vw) {
    __shared__ float Xs[BK][BM + 4];   // +4 keeps 16B alignment & kills conflicts
    __shared__ float Ws[BK][BN];
    int m0 = blockIdx.x * BM;
    int n0 = blockIdx.y * BN;
    int tid = threadIdx.x;
    int tx = tid & 15, ty = tid >> 4;
    float acc[4][4] = {};

    for (int k0 = 0; k0 < KTOT; k0 += BK) {
#pragma unroll
        for (int i = 0; i < 4; i++) {           // Xs: 64 rows x 16 k
            int e = tid + i * 256;
            int row = e >> 4, k = e & 15;
            int kg = k0 + k;
            int grow = m0 + row;
            Xs[k][row] = (kg < E) ? enc[(size_t)grow * E + kg]
                                  : g_loc[grow * NF + (kg - E)];
        }
#pragma unroll
        for (int i = 0; i < 4; i++) {           // Ws: 16 k x 64 n
            int e = tid + i * 256;
            int k = e >> 6, n = e & 63;
            int kg = k0 + k;
            Ws[k][n] = (kg < E) ? We[kg * A + n0 + n]
                                : Wl[(kg - E) * A + n0 + n];
        }
        __syncthreads();
#pragma unroll
        for (int kk = 0; kk < BK; kk++) {
            float xv[4], wv[4];
#pragma unroll
            for (int i = 0; i < 4; i++) xv[i] = Xs[kk][ty * 4 + i];
#pragma unroll
            for (int j = 0; j < 4; j++) wv[j] = Ws[kk][tx * 4 + j];
#pragma unroll
            for (int i = 0; i < 4; i++)
#pragma unroll
                for (int j = 0; j < 4; j++)
                    acc[i][j] += xv[i] * wv[j];
        }
        __syncthreads();
    }

    // epilogue: partial energy = sum_n v[n] * tanh(acc + dproj[b,n])
    float vv[4];
#pragma unroll
    for (int j = 0; j < 4; j++) vv[j] = vw[n0 + tx * 4 + j];
#pragma unroll
    for (int i = 0; i < 4; i++) {
        int row = m0 + ty * 4 + i;
        int b = row / T;
        float part = 0.f;
#pragma unroll
        for (int j = 0; j < 4; j++) {
            float z = acc[i][j] + g_dproj[b * A + n0 + tx * 4 + j];
            part += vv[j] * tanhf(z);
        }
        // reduce over the 16 tx lanes sharing this row (within warp half)
        part += __shfl_xor_sync(0xffffffffu, part, 1);
        part += __shfl_xor_sync(0xffffffffu, part, 2);
        part += __shfl_xor_sync(0xffffffffu, part, 4);
        part += __shfl_xor_sync(0xffffffffu, part, 8);
        if (tx == 0) atomicAdd(&g_energy[row], part);
    }
}

// ---------------------------------------------------------------------------
// masked softmax over T, one block per batch row
__global__ void k_softmax(const int* __restrict__ mask, float* __restrict__ attn) {
    __shared__ float red[256];
    int b = blockIdx.x, tid = threadIdx.x;
    float le[8];
    float mx = -1e30f;
#pragma unroll
    for (int i = 0; i < 8; i++) {
        int t = tid + i * 256;
        float e = -1e30f;
        if (t < T) e = (mask[b * T + t] == 0) ? -1e9f : g_energy[b * T + t];
        le[i] = e;
        mx = fmaxf(mx, e);
    }
    red[tid] = mx; __syncthreads();
    for (int s = 128; s > 0; s >>= 1) {
        if (tid < s) red[tid] = fmaxf(red[tid], red[tid + s]);
        __syncthreads();
    }
    mx = red[0]; __syncthreads();
    float sum = 0.f;
#pragma unroll
    for (int i = 0; i < 8; i++) {
        int t = tid + i * 256;
        if (t < T) { le[i] = __expf(le[i] - mx); sum += le[i]; }
    }
    red[tid] = sum; __syncthreads();
    for (int s = 128; s > 0; s >>= 1) {
        if (tid < s) red[tid] += red[tid + s];
        __syncthreads();
    }
    float inv = 1.f / red[0];
#pragma unroll
    for (int i = 0; i < 8; i++) {
        int t = tid + i * 256;
        if (t < T) attn[b * T + t] = le[i] * inv;
    }
}

// ---------------------------------------------------------------------------
// context[b,e] = sum_t attn[b,t] * enc[b,t,e]   (T split for occupancy)
#define TSPLIT 8
__global__ void k_context(const float* __restrict__ enc, const float* __restrict__ attn,
                          float* __restrict__ ctx) {
    int b = blockIdx.x, s = blockIdx.y;
    int e = threadIdx.x;                 // 512 threads == E
    int t0 = s * (T / TSPLIT), t1 = t0 + (T / TSPLIT);
    float acc = 0.f;
    for (int t = t0; t < t1; t++)
        acc += attn[b * T + t] * enc[((size_t)b * T + t) * E + e];
    atomicAdd(&ctx[b * E + e], acc);
}

// ---------------------------------------------------------------------------
extern "C" void kernel_launch(void* const* d_in, const int* in_sizes, int n_in,
                              void* d_out, int out_size) {
    const float* dec  = (const float*)d_in[0];   // decoder_state [B,D]
    const float* enc  = (const float*)d_in[1];   // encoder_outputs [B,T,E]
    const float* prev = (const float*)d_in[2];   // prev_attention_weights [B,T]
    const int*   mask = (const int*)  d_in[3];   // encoder_mask [B,T]
    const float* cw   = (const float*)d_in[4];   // conv_w [NF,1,KW]
    const float* We   = (const float*)d_in[5];   // W_enc [E,A]
    const float* Wd   = (const float*)d_in[6];   // W_dec [D,A]
    const float* Wl   = (const float*)d_in[7];   // W_loc [NF,A]
    const float* vw   = (const float*)d_in[8];   // v_w [A]

    float* ctx  = (float*)d_out;                 // context [B,E]
    float* attn = (float*)d_out + B * E;         // attn    [B,T]

    k_init<<<(BT + 255) / 256, 256>>>(ctx);
    k_dproj<<<B, 256>>>(dec, Wd);
    k_conv<<<dim3((T + CT - 1) / CT, B), 256>>>(prev, cw);
    k_gemm<<<dim3(BT / BM, A / BN), 256>>>(enc, We, Wl, vw);
    k_softmax<<<B, 256>>>(mask, attn);
    k_context<<<dim3(B, TSPLIT), E>>>(enc, attn, ctx);
}

// round 3
// speedup vs baseline: 1.9901x; 1.9901x over previous
#include <cuda_runtime.h>
#include <cuda_bf16.h>
#include <math.h>
#include <stdint.h>

#define B   64
#define T   2000
#define E   512
#define D   1024
#define A   256
#define NF  32
#define KW  31
#define PAD 15
#define BT  (B*T)
#define KTOT 544          // 512 + 32, = 17 * 32
#define KC   32
#define NCHUNK 17

// ---------------- scratch globals (no allocation allowed) -------------------
__device__ float g_loc[BT * NF];           // location features [B,T,NF]
__device__ float g_dproj[B * A];           // decoder projection [B,A]
__device__ float g_energy[BT];             // pre-softmax energies
__device__ __nv_bfloat16 g_Whi[A * KTOT];  // W^T hi  [n=256][k=544]
__device__ __nv_bfloat16 g_Wlo[A * KTOT];  // W^T lo

// ---------------- smem layout (bytes) ---------------------------------------
// stage: Xhi 128*80 | Xlo 128*80 | Whi 256*80 | Wlo 256*80  (80B padded rows)
#define ST_BYTES 61440
#define XHI_O(s) ((s)*ST_BYTES + 0)
#define XLO_O(s) ((s)*ST_BYTES + 10240)
#define WHI_O(s) ((s)*ST_BYTES + 20480)
#define WLO_O(s) ((s)*ST_BYTES + 40960)
#define SV_O   122880
#define SDP_O  123904
#define SRED_O 125952
#define SMEM_TOTAL 128000

// ---------------- PTX helpers -----------------------------------------------
__device__ __forceinline__ uint32_t smem_u32(const void* p) {
    uint32_t a;
    asm("{ .reg .u64 t; cvta.to.shared.u64 t, %1; cvt.u32.u64 %0, t; }" : "=r"(a) : "l"(p));
    return a;
}
__device__ __forceinline__ void ldsm4(uint32_t (&r)[4], uint32_t a) {
    asm volatile("ldmatrix.sync.aligned.m8n8.x4.shared.b16 {%0,%1,%2,%3}, [%4];"
                 : "=r"(r[0]), "=r"(r[1]), "=r"(r[2]), "=r"(r[3]) : "r"(a));
}
__device__ __forceinline__ void mma16816(float (&d)[4], const uint32_t (&a)[4],
                                         uint32_t b0, uint32_t b1) {
    asm volatile(
        "mma.sync.aligned.m16n8k16.row.col.f32.bf16.bf16.f32 "
        "{%0,%1,%2,%3}, {%4,%5,%6,%7}, {%8,%9}, {%0,%1,%2,%3};"
        : "+f"(d[0]), "+f"(d[1]), "+f"(d[2]), "+f"(d[3])
        : "r"(a[0]), "r"(a[1]), "r"(a[2]), "r"(a[3]), "r"(b0), "r"(b1));
}
__device__ __forceinline__ void cp16(uint32_t dst, const void* src) {
    asm volatile("cp.async.cg.shared.global [%0], [%1], 16;" :: "r"(dst), "l"(src));
}
__device__ __forceinline__ void cp_commit() {
    asm volatile("cp.async.commit_group;" ::: "memory");
}
__device__ __forceinline__ void sts128(uint32_t a, uint32_t x, uint32_t y, uint32_t z, uint32_t w) {
    asm volatile("st.shared.v4.b32 [%0], {%1,%2,%3,%4};" :: "r"(a), "r"(x), "r"(y), "r"(z), "r"(w) : "memory");
}
__device__ __forceinline__ float fast_tanh(float z) {
    float e = __expf(2.f * z);
    return 1.f - __fdividef(2.f, e + 1.f);
}

// ---------------------------------------------------------------------------
__global__ void k_init(float* __restrict__ ctx) {
    int i = blockIdx.x * blockDim.x + threadIdx.x;
    if (i < B * E) ctx[i] = 0.f;
}

// W^T split to bf16 hi/lo: g_W*[n][k], k contiguous
__global__ void k_prep_w(const float* __restrict__ We, const float* __restrict__ Wl) {
    int i = blockIdx.x * 256 + threadIdx.x;
    if (i >= A * KTOT) return;
    int n = i / KTOT, k = i % KTOT;
    float w = (k < E) ? We[k * A + n] : Wl[(k - E) * A + n];
    __nv_bfloat16 h = __float2bfloat16(w);
    g_Whi[i] = h;
    g_Wlo[i] = __float2bfloat16(w - __bfloat162float(h));
}

__global__ void k_dproj(const float* __restrict__ dec, const float* __restrict__ Wd) {
    __shared__ float sdec[256];
    int b = blockIdx.x, a = threadIdx.x;
    float acc = 0.f;
    for (int d0 = 0; d0 < D; d0 += 256) {
        __syncthreads();
        sdec[a] = dec[b * D + d0 + a];
        __syncthreads();
#pragma unroll 8
        for (int dd = 0; dd < 256; dd++) acc += sdec[dd] * Wd[(d0 + dd) * A + a];
    }
    g_dproj[b * A + a] = acc;
}

#define CT 128
__global__ void k_conv(const float* __restrict__ prev, const float* __restrict__ cw) {
    __shared__ float sp[CT + KW - 1];
    __shared__ float sw[NF * KW];
    int b = blockIdx.y, t0 = blockIdx.x * CT;
    int tid = threadIdx.x;
    for (int i = tid; i < NF * KW; i += 256) sw[i] = cw[i];
    for (int i = tid; i < CT + KW - 1; i += 256) {
        int t = t0 + i - PAD;
        sp[i] = (t >= 0 && t < T) ? prev[b * T + t] : 0.f;
    }
    __syncthreads();
    for (int i = tid; i < CT * NF; i += 256) {
        int tl = i / NF, f = i % NF;
        int t = t0 + tl;
        if (t < T) {
            float acc = 0.f;
#pragma unroll
            for (int k = 0; k < KW; k++) acc += sw[f * KW + k] * sp[tl + k];
            g_loc[(b * T + t) * NF + f] = acc;
        }
    }
}

// ---------------------------------------------------------------------------
// fill one stage: X (LDG fp32 -> split bf16 -> STS) + W (cp.async of prepped bf16)
__device__ __forceinline__ void fill_stage(uint32_t sb, int s, int c, int m0,
                                           const float* __restrict__ enc, int tid) {
    int k0 = c * KC;
    // ---- X: 128 rows x 32 k. thread -> (row=tid>>1, half=tid&1 -> 16 k) ----
    int row = tid >> 1, kh = tid & 1;
    int gk = k0 + kh * 16;
    const float4* src = (gk < E)
        ? (const float4*)(enc + (size_t)(m0 + row) * E + gk)
        : (const float4*)(g_loc + (size_t)(m0 + row) * NF + (gk - E));
    float x[16];
#pragma unroll
    for (int i = 0; i < 4; i++) {
        float4 q = src[i];
        x[4*i] = q.x; x[4*i+1] = q.y; x[4*i+2] = q.z; x[4*i+3] = q.w;
    }
    uint32_t hp[8], lp[8];
#pragma unroll
    for (int i = 0; i < 8; i++) {
        __nv_bfloat16 h0 = __float2bfloat16(x[2*i]);
        __nv_bfloat16 h1 = __float2bfloat16(x[2*i+1]);
        __nv_bfloat16 l0 = __float2bfloat16(x[2*i]   - __bfloat162float(h0));
        __nv_bfloat16 l1 = __float2bfloat16(x[2*i+1] - __bfloat162float(h1));
        hp[i] = (uint32_t)__bfloat16_as_ushort(h0) | ((uint32_t)__bfloat16_as_ushort(h1) << 16);
        lp[i] = (uint32_t)__bfloat16_as_ushort(l0) | ((uint32_t)__bfloat16_as_ushort(l1) << 16);
    }
    uint32_t xo = (uint32_t)row * 80u + (uint32_t)kh * 32u;
    sts128(sb + XHI_O(s) + xo,      hp[0], hp[1], hp[2], hp[3]);
    sts128(sb + XHI_O(s) + xo + 16, hp[4], hp[5], hp[6], hp[7]);
    sts128(sb + XLO_O(s) + xo,      lp[0], lp[1], lp[2], lp[3]);
    sts128(sb + XLO_O(s) + xo + 16, lp[4], lp[5], lp[6], lp[7]);
    // ---- W: 256 rows x 32 k bf16 hi/lo via cp.async ----
    int n = tid;
    const __nv_bfloat16* wh = g_Whi + (size_t)n * KTOT + k0;
    const __nv_bfloat16* wl = g_Wlo + (size_t)n * KTOT + k0;
    uint32_t wha = sb + WHI_O(s) + (uint32_t)n * 80u;
    uint32_t wla = sb + WLO_O(s) + (uint32_t)n * 80u;
#pragma unroll
    for (int g = 0; g < 4; g++) {
        cp16(wha + g * 16, wh + g * 8);
        cp16(wla + g * 16, wl + g * 8);
    }
    cp_commit();
}

__device__ __forceinline__ void mma_stage(uint32_t sb, int s, int mwarp, int nwarp,
                                          int lane, float (&acc)[4][8][4]) {
    uint32_t xhi = sb + XHI_O(s), xlo = sb + XLO_O(s);
    uint32_t whi = sb + WHI_O(s), wlo = sb + WLO_O(s);
    int lrow = lane & 15, lsel = (lane >> 4) & 1;
#pragma unroll
    for (int kh = 0; kh < 2; kh++) {
        uint32_t kof = (uint32_t)kh * 32u + (uint32_t)lsel * 16u;
        uint32_t ahi[4][4], alo[4][4];
#pragma unroll
        for (int mt = 0; mt < 4; mt++) {
            uint32_t ra = (uint32_t)(mwarp * 64 + mt * 16 + lrow) * 80u + kof;
            ldsm4(ahi[mt], xhi + ra);
            ldsm4(alo[mt], xlo + ra);
        }
#pragma unroll
        for (int nt = 0; nt < 4; nt++) {
            uint32_t rb = (uint32_t)(nwarp * 64 + nt * 16 + lrow) * 80u + kof;
            uint32_t bb[4];
            ldsm4(bb, whi + rb);
#pragma unroll
            for (int mt = 0; mt < 4; mt++) {
                mma16816(acc[mt][nt*2],   ahi[mt], bb[0], bb[2]);
                mma16816(acc[mt][nt*2+1], ahi[mt], bb[1], bb[3]);
            }
#pragma unroll
            for (int mt = 0; mt < 4; mt++) {
                mma16816(acc[mt][nt*2],   alo[mt], bb[0], bb[2]);
                mma16816(acc[mt][nt*2+1], alo[mt], bb[1], bb[3]);
            }
            ldsm4(bb, wlo + rb);
#pragma unroll
            for (int mt = 0; mt < 4; mt++) {
                mma16816(acc[mt][nt*2],   ahi[mt], bb[0], bb[2]);
                mma16816(acc[mt][nt*2+1], ahi[mt], bb[1], bb[3]);
            }
        }
    }
}

// tcgen05 unavailable on this build target -> HMMA via mma.sync, split-bf16 x3
__global__ void __launch_bounds__(256, 1) k_gemm_mma(const float* __restrict__ enc,
                                                     const float* __restrict__ vw) {
    extern __shared__ char smem_raw[];
    uint32_t sb = smem_u32(smem_raw);
    float* sv   = (float*)(smem_raw + SV_O);
    float* sdp  = (float*)(smem_raw + SDP_O);
    float* sred = (float*)(smem_raw + SRED_O);

    int tid = threadIdx.x, lane = tid & 31, wid = tid >> 5;
    int mwarp = wid >> 2, nwarp = wid & 3;
    int m0 = blockIdx.x * 128;
    int b0 = m0 / T;

    sv[tid]        = vw[tid];
    sdp[tid]       = g_dproj[b0 * A + tid];
    sdp[256 + tid] = g_dproj[((m0 + 127) / T) * A + tid];

    float acc[4][8][4];
#pragma unroll
    for (int i = 0; i < 4; i++)
#pragma unroll
        for (int j = 0; j < 8; j++)
#pragma unroll
            for (int k = 0; k < 4; k++) acc[i][j][k] = 0.f;

    fill_stage(sb, 0, 0, m0, enc, tid);
    for (int c = 0; c < NCHUNK; ++c) {
        if (c + 1 < NCHUNK) {
            fill_stage(sb, (c + 1) & 1, c + 1, m0, enc, tid);
            asm volatile("cp.async.wait_group 1;" ::: "memory");
        } else {
            asm volatile("cp.async.wait_group 0;" ::: "memory");
        }
        __syncthreads();
        mma_stage(sb, c & 1, mwarp, nwarp, lane, acc);
        __syncthreads();
    }

    // ---- epilogue: energy[row] = sum_n v[n] * tanh(acc + dproj[b,n]) ----
#pragma unroll
    for (int mt = 0; mt < 4; mt++)
#pragma unroll
        for (int h = 0; h < 2; h++) {
            int rl = mwarp * 64 + mt * 16 + (lane >> 2) + h * 8;
            const float* dp = sdp + (((m0 + rl) / T == b0) ? 0 : 256);
            float part = 0.f;
#pragma unroll
            for (int nt8 = 0; nt8 < 8; nt8++) {
                int n = nwarp * 64 + nt8 * 8 + (lane & 3) * 2;
                float z0 = acc[mt][nt8][h*2]   + dp[n];
                float z1 = acc[mt][nt8][h*2+1] + dp[n+1];
                part += sv[n] * fast_tanh(z0) + sv[n+1] * fast_tanh(z1);
            }
            part += __shfl_xor_sync(0xffffffffu, part, 1);
            part += __shfl_xor_sync(0xffffffffu, part, 2);
            if ((lane & 3) == 0) sred[nwarp * 128 + rl] = part;
        }
    __syncthreads();
    if (tid < 128)
        g_energy[m0 + tid] = sred[tid] + sred[128 + tid] + sred[256 + tid] + sred[384 + tid];
}

// ---------------------------------------------------------------------------
__global__ void k_softmax(const int* __restrict__ mask, float* __restrict__ attn) {
    __shared__ float red[256];
    int b = blockIdx.x, tid = threadIdx.x;
    float le[8];
    float mx = -1e30f;
#pragma unroll
    for (int i = 0; i < 8; i++) {
        int t = tid + i * 256;
        float e = -1e30f;
        if (t < T) e = (mask[b * T + t] == 0) ? -1e9f : g_energy[b * T + t];
        le[i] = e;
        mx = fmaxf(mx, e);
    }
    red[tid] = mx; __syncthreads();
    for (int s = 128; s > 0; s >>= 1) {
        if (tid < s) red[tid] = fmaxf(red[tid], red[tid + s]);
        __syncthreads();
    }
    mx = red[0]; __syncthreads();
    float sum = 0.f;
#pragma unroll
    for (int i = 0; i < 8; i++) {
        int t = tid + i * 256;
        if (t < T) { le[i] = __expf(le[i] - mx); sum += le[i]; }
    }
    red[tid] = sum; __syncthreads();
    for (int s = 128; s > 0; s >>= 1) {
        if (tid < s) red[tid] += red[tid + s];
        __syncthreads();
    }
    float inv = 1.f / red[0];
#pragma unroll
    for (int i = 0; i < 8; i++) {
        int t = tid + i * 256;
        if (t < T) attn[b * T + t] = le[i] * inv;
    }
}

#define TSPLIT 8
__global__ void k_context(const float* __restrict__ enc, const float* __restrict__ attn,
                          float* __restrict__ ctx) {
    int b = blockIdx.x, s = blockIdx.y;
    int e = threadIdx.x;
    int t0 = s * (T / TSPLIT), t1 = t0 + (T / TSPLIT);
    float acc = 0.f;
    for (int t = t0; t < t1; t++)
        acc += attn[b * T + t] * enc[((size_t)b * T + t) * E + e];
    atomicAdd(&ctx[b * E + e], acc);
}

// ---------------------------------------------------------------------------
extern "C" void kernel_launch(void* const* d_in, const int* in_sizes, int n_in,
                              void* d_out, int out_size) {
    const float* dec  = (const float*)d_in[0];
    const float* enc  = (const float*)d_in[1];
    const float* prev = (const float*)d_in[2];
    const int*   mask = (const int*)  d_in[3];
    const float* cw   = (const float*)d_in[4];
    const float* We   = (const float*)d_in[5];
    const float* Wd   = (const float*)d_in[6];
    const float* Wl   = (const float*)d_in[7];
    const float* vw   = (const float*)d_in[8];

    float* ctx  = (float*)d_out;
    float* attn = (float*)d_out + B * E;

    static int smem_set = 0;
    if (!smem_set) {
        cudaFuncSetAttribute(k_gemm_mma, cudaFuncAttributeMaxDynamicSharedMemorySize, SMEM_TOTAL);
        smem_set = 1;
    }

    k_init<<<(B * E + 255) / 256, 256>>>(ctx);
    k_prep_w<<<(A * KTOT + 255) / 256, 256>>>(We, Wl);
    k_dproj<<<B, 256>>>(dec, Wd);
    k_conv<<<dim3((T + CT - 1) / CT, B), 256>>>(prev, cw);
    k_gemm_mma<<<BT / 128, 256, SMEM_TOTAL>>>(enc, vw);
    k_softmax<<<B, 256>>>(mask, attn);
    k_context<<<dim3(B, TSPLIT), E>>>(enc, attn, ctx);
}

// round 4
// speedup vs baseline: 2.1950x; 1.1030x over previous
#include <cuda_runtime.h>
#include <cuda_bf16.h>
#include <math.h>
#include <stdint.h>

#define B   64
#define T   2000
#define E   512
#define D   1024
#define A   256
#define NF  32
#define KW  31
#define PAD 15
#define BT  (B*T)
#define KTOT 544          // 512 + 32, = 17 * 32
#define KC   32
#define NCHUNK 17

// ---------------- scratch globals (no allocation allowed) -------------------
__device__ float g_loc[BT * NF];           // location features [B,T,NF]
__device__ float g_dproj[B * A];           // decoder projection [B,A]
__device__ float g_energy[BT];             // pre-softmax energies
__device__ __nv_bfloat16 g_Whi[A * KTOT];  // W^T hi  [n=256][k=544]
__device__ __nv_bfloat16 g_Wlo[A * KTOT];  // W^T lo

// ---------------- smem layout (bytes) ---------------------------------------
// stage: Xhi 128*80 | Xlo 128*80 | Whi 256*80 | Wlo 256*80  (80B padded rows)
#define ST_BYTES 61440
#define XHI_O(s) ((s)*ST_BYTES + 0)
#define XLO_O(s) ((s)*ST_BYTES + 10240)
#define WHI_O(s) ((s)*ST_BYTES + 20480)
#define WLO_O(s) ((s)*ST_BYTES + 40960)
#define SV_O   122880
#define SDP_O  123904
#define SRED_O 125952
#define SMEM_TOTAL 128000

// ---------------- PTX helpers -----------------------------------------------
__device__ __forceinline__ uint32_t smem_u32(const void* p) {
    uint32_t a;
    asm("{ .reg .u64 t; cvta.to.shared.u64 t, %1; cvt.u32.u64 %0, t; }" : "=r"(a) : "l"(p));
    return a;
}
__device__ __forceinline__ void ldsm4(uint32_t (&r)[4], uint32_t a) {
    asm volatile("ldmatrix.sync.aligned.m8n8.x4.shared.b16 {%0,%1,%2,%3}, [%4];"
                 : "=r"(r[0]), "=r"(r[1]), "=r"(r[2]), "=r"(r[3]) : "r"(a));
}
__device__ __forceinline__ void mma16816(float (&d)[4], const uint32_t (&a)[4],
                                         uint32_t b0, uint32_t b1) {
    asm volatile(
        "mma.sync.aligned.m16n8k16.row.col.f32.bf16.bf16.f32 "
        "{%0,%1,%2,%3}, {%4,%5,%6,%7}, {%8,%9}, {%0,%1,%2,%3};"
        : "+f"(d[0]), "+f"(d[1]), "+f"(d[2]), "+f"(d[3])
        : "r"(a[0]), "r"(a[1]), "r"(a[2]), "r"(a[3]), "r"(b0), "r"(b1));
}
__device__ __forceinline__ void cp16(uint32_t dst, const void* src) {
    asm volatile("cp.async.cg.shared.global [%0], [%1], 16;" :: "r"(dst), "l"(src));
}
__device__ __forceinline__ void cp_commit() {
    asm volatile("cp.async.commit_group;" ::: "memory");
}
__device__ __forceinline__ void cp_wait0() {
    asm volatile("cp.async.wait_group 0;" ::: "memory");
}
__device__ __forceinline__ void sts128(uint32_t a, uint32_t x, uint32_t y, uint32_t z, uint32_t w) {
    asm volatile("st.shared.v4.b32 [%0], {%1,%2,%3,%4};" :: "r"(a), "r"(x), "r"(y), "r"(z), "r"(w) : "memory");
}
__device__ __forceinline__ float fast_tanh(float z) {
    float e = __expf(2.f * z);
    return 1.f - __fdividef(2.f, e + 1.f);
}

// ---------------------------------------------------------------------------
__global__ void k_init(float* __restrict__ ctx) {
    int i = blockIdx.x * blockDim.x + threadIdx.x;
    if (i < B * E) ctx[i] = 0.f;
}

// W^T split to bf16 hi/lo: g_W*[n][k], k contiguous
__global__ void k_prep_w(const float* __restrict__ We, const float* __restrict__ Wl) {
    int i = blockIdx.x * 256 + threadIdx.x;
    if (i >= A * KTOT) return;
    int n = i / KTOT, k = i % KTOT;
    float w = (k < E) ? We[k * A + n] : Wl[(k - E) * A + n];
    __nv_bfloat16 h = __float2bfloat16(w);
    g_Whi[i] = h;
    g_Wlo[i] = __float2bfloat16(w - __bfloat162float(h));
}

__global__ void k_dproj(const float* __restrict__ dec, const float* __restrict__ Wd) {
    __shared__ float sdec[256];
    int b = blockIdx.x, a = threadIdx.x;
    float acc = 0.f;
    for (int d0 = 0; d0 < D; d0 += 256) {
        __syncthreads();
        sdec[a] = dec[b * D + d0 + a];
        __syncthreads();
#pragma unroll 8
        for (int dd = 0; dd < 256; dd++) acc += sdec[dd] * Wd[(d0 + dd) * A + a];
    }
    g_dproj[b * A + a] = acc;
}

// register-weight FIR conv: f = lane (NF==32), sp broadcast from smem
#define CTV 256
__global__ void k_conv(const float* __restrict__ prev, const float* __restrict__ cw) {
    __shared__ float sp[CTV + KW - 1];
    int b = blockIdx.y, t0 = blockIdx.x * CTV;
    int tid = threadIdx.x, lane = tid & 31, w = tid >> 5;
    for (int i = tid; i < CTV + KW - 1; i += 256) {
        int t = t0 + i - PAD;
        sp[i] = (t >= 0 && t < T) ? prev[b * T + t] : 0.f;
    }
    float wr[KW];
#pragma unroll
    for (int k = 0; k < KW; k++) wr[k] = cw[lane * KW + k];
    __syncthreads();
    int tl0 = w * 32;
#pragma unroll 4
    for (int j = 0; j < 32; j++) {
        int tl = tl0 + j;
        int t = t0 + tl;
        float acc = 0.f;
#pragma unroll
        for (int k = 0; k < KW; k++) acc += wr[k] * sp[tl + k];
        if (t < T) g_loc[((size_t)b * T + t) * NF + lane] = acc;
    }
}

// ---------------------------------------------------------------------------
// X chunk LDG: 16 fp32 per thread (row = tid>>1, khalf = tid&1)
__device__ __forceinline__ void ldg_x(int c, int m0, int tid,
                                      const float* __restrict__ enc, float (&x)[16]) {
    int row = tid >> 1, kh = tid & 1;
    int gk = c * KC + kh * 16;
    const float4* src = (gk < E)
        ? (const float4*)(enc + (size_t)(m0 + row) * E + gk)
        : (const float4*)(g_loc + (size_t)(m0 + row) * NF + (gk - E));
#pragma unroll
    for (int i = 0; i < 4; i++) {
        float4 q = src[i];
        x[4*i] = q.x; x[4*i+1] = q.y; x[4*i+2] = q.z; x[4*i+3] = q.w;
    }
}

// convert regs -> bf16 hi/lo and store into stage s
__device__ __forceinline__ void sts_x(uint32_t sb, int s, int tid, const float (&x)[16]) {
    int row = tid >> 1, kh = tid & 1;
    uint32_t hp[8], lp[8];
#pragma unroll
    for (int i = 0; i < 8; i++) {
        __nv_bfloat16 h0 = __float2bfloat16(x[2*i]);
        __nv_bfloat16 h1 = __float2bfloat16(x[2*i+1]);
        __nv_bfloat16 l0 = __float2bfloat16(x[2*i]   - __bfloat162float(h0));
        __nv_bfloat16 l1 = __float2bfloat16(x[2*i+1] - __bfloat162float(h1));
        hp[i] = (uint32_t)__bfloat16_as_ushort(h0) | ((uint32_t)__bfloat16_as_ushort(h1) << 16);
        lp[i] = (uint32_t)__bfloat16_as_ushort(l0) | ((uint32_t)__bfloat16_as_ushort(l1) << 16);
    }
    uint32_t xo = (uint32_t)row * 80u + (uint32_t)kh * 32u;
    sts128(sb + XHI_O(s) + xo,      hp[0], hp[1], hp[2], hp[3]);
    sts128(sb + XHI_O(s) + xo + 16, hp[4], hp[5], hp[6], hp[7]);
    sts128(sb + XLO_O(s) + xo,      lp[0], lp[1], lp[2], lp[3]);
    sts128(sb + XLO_O(s) + xo + 16, lp[4], lp[5], lp[6], lp[7]);
}

// W chunk c -> stage s via cp.async (one commit group)
__device__ __forceinline__ void cp_w(uint32_t sb, int s, int c, int tid) {
    int k0 = c * KC;
    const __nv_bfloat16* wh = g_Whi + (size_t)tid * KTOT + k0;
    const __nv_bfloat16* wl = g_Wlo + (size_t)tid * KTOT + k0;
    uint32_t wha = sb + WHI_O(s) + (uint32_t)tid * 80u;
    uint32_t wla = sb + WLO_O(s) + (uint32_t)tid * 80u;
#pragma unroll
    for (int g = 0; g < 4; g++) {
        cp16(wha + g * 16, wh + g * 8);
        cp16(wla + g * 16, wl + g * 8);
    }
    cp_commit();
}

__device__ __forceinline__ void mma_stage(uint32_t sb, int s, int mwarp, int nwarp,
                                          int lane, float (&acc)[4][8][4]) {
    uint32_t xhi = sb + XHI_O(s), xlo = sb + XLO_O(s);
    uint32_t whi = sb + WHI_O(s), wlo = sb + WLO_O(s);
    int lrow = lane & 15, lsel = (lane >> 4) & 1;
#pragma unroll
    for (int kh = 0; kh < 2; kh++) {
        uint32_t kof = (uint32_t)kh * 32u + (uint32_t)lsel * 16u;
        uint32_t ahi[4][4], alo[4][4];
#pragma unroll
        for (int mt = 0; mt < 4; mt++) {
            uint32_t ra = (uint32_t)(mwarp * 64 + mt * 16 + lrow) * 80u + kof;
            ldsm4(ahi[mt], xhi + ra);
            ldsm4(alo[mt], xlo + ra);
        }
#pragma unroll
        for (int nt = 0; nt < 4; nt++) {
            uint32_t rb = (uint32_t)(nwarp * 64 + nt * 16 + lrow) * 80u + kof;
            uint32_t bb[4];
            ldsm4(bb, whi + rb);
#pragma unroll
            for (int mt = 0; mt < 4; mt++) {
                mma16816(acc[mt][nt*2],   ahi[mt], bb[0], bb[2]);
                mma16816(acc[mt][nt*2+1], ahi[mt], bb[1], bb[3]);
            }
#pragma unroll
            for (int mt = 0; mt < 4; mt++) {
                mma16816(acc[mt][nt*2],   alo[mt], bb[0], bb[2]);
                mma16816(acc[mt][nt*2+1], alo[mt], bb[1], bb[3]);
            }
            ldsm4(bb, wlo + rb);
#pragma unroll
            for (int mt = 0; mt < 4; mt++) {
                mma16816(acc[mt][nt*2],   ahi[mt], bb[0], bb[2]);
                mma16816(acc[mt][nt*2+1], ahi[mt], bb[1], bb[3]);
            }
        }
    }
}

// HMMA split-bf16 x3 GEMM with software-pipelined X (LDG 2 stages ahead)
__global__ void __launch_bounds__(256, 1) k_gemm_mma(const float* __restrict__ enc,
                                                     const float* __restrict__ vw) {
    extern __shared__ char smem_raw[];
    uint32_t sb = smem_u32(smem_raw);
    float* sv   = (float*)(smem_raw + SV_O);
    float* sdp  = (float*)(smem_raw + SDP_O);
    float* sred = (float*)(smem_raw + SRED_O);

    int tid = threadIdx.x, lane = tid & 31, wid = tid >> 5;
    int mwarp = wid >> 2, nwarp = wid & 3;
    int m0 = blockIdx.x * 128;
    int b0 = m0 / T;

    sv[tid]        = vw[tid];
    sdp[tid]       = g_dproj[b0 * A + tid];
    sdp[256 + tid] = g_dproj[((m0 + 127) / T) * A + tid];

    float acc[4][8][4];
#pragma unroll
    for (int i = 0; i < 4; i++)
#pragma unroll
        for (int j = 0; j < 8; j++)
#pragma unroll
            for (int k = 0; k < 4; k++) acc[i][j][k] = 0.f;

    float xr[16];
    // prologue: stage0 fully, stage1 W + X regs
    ldg_x(0, m0, tid, enc, xr);
    cp_w(sb, 0, 0, tid);
    sts_x(sb, 0, tid, xr);
    ldg_x(1, m0, tid, enc, xr);
    cp_w(sb, 1, 1, tid);
    asm volatile("cp.async.wait_group 1;" ::: "memory");  // W0 done (W1 may fly)
    __syncthreads();                                      // stage0 visible

    for (int c = 0; c < NCHUNK; ++c) {
        mma_stage(sb, c & 1, mwarp, nwarp, lane, acc);
        if (c + 1 < NCHUNK) sts_x(sb, (c + 1) & 1, tid, xr);  // others read buf c&1: safe
        cp_wait0();                                            // W[c+1] landed (per-thread)
        __syncthreads();                                       // publish X[c+1] STS + W[c+1]
        if (c + 2 < NCHUNK) {
            ldg_x(c + 2, m0, tid, enc, xr);    // consumed after mma(c+1): latency hidden
            cp_w(sb, (c + 2) & 1, c + 2, tid); // buf (c&1) done being read after sync
        }
    }

    // ---- epilogue: energy[row] = sum_n v[n] * tanh(acc + dproj[b,n]) ----
#pragma unroll
    for (int mt = 0; mt < 4; mt++)
#pragma unroll
        for (int h = 0; h < 2; h++) {
            int rl = mwarp * 64 + mt * 16 + (lane >> 2) + h * 8;
            const float* dp = sdp + (((m0 + rl) / T == b0) ? 0 : 256);
            float part = 0.f;
#pragma unroll
            for (int nt8 = 0; nt8 < 8; nt8++) {
                int n = nwarp * 64 + nt8 * 8 + (lane & 3) * 2;
                float z0 = acc[mt][nt8][h*2]   + dp[n];
                float z1 = acc[mt][nt8][h*2+1] + dp[n+1];
                part += sv[n] * fast_tanh(z0) + sv[n+1] * fast_tanh(z1);
            }
            part += __shfl_xor_sync(0xffffffffu, part, 1);
            part += __shfl_xor_sync(0xffffffffu, part, 2);
            if ((lane & 3) == 0) sred[nwarp * 128 + rl] = part;
        }
    __syncthreads();
    if (tid < 128)
        g_energy[m0 + tid] = sred[tid] + sred[128 + tid] + sred[256 + tid] + sred[384 + tid];
}

// ---------------------------------------------------------------------------
__global__ void k_softmax(const int* __restrict__ mask, float* __restrict__ attn) {
    __shared__ float red[256];
    int b = blockIdx.x, tid = threadIdx.x;
    float le[8];
    float mx = -1e30f;
#pragma unroll
    for (int i = 0; i < 8; i++) {
        int t = tid + i * 256;
        float e = -1e30f;
        if (t < T) e = (mask[b * T + t] == 0) ? -1e9f : g_energy[b * T + t];
        le[i] = e;
        mx = fmaxf(mx, e);
    }
    red[tid] = mx; __syncthreads();
    for (int s = 128; s > 0; s >>= 1) {
        if (tid < s) red[tid] = fmaxf(red[tid], red[tid + s]);
        __syncthreads();
    }
    mx = red[0]; __syncthreads();
    float sum = 0.f;
#pragma unroll
    for (int i = 0; i < 8; i++) {
        int t = tid + i * 256;
        if (t < T) { le[i] = __expf(le[i] - mx); sum += le[i]; }
    }
    red[tid] = sum; __syncthreads();
    for (int s = 128; s > 0; s >>= 1) {
        if (tid < s) red[tid] += red[tid + s];
        __syncthreads();
    }
    float inv = 1.f / red[0];
#pragma unroll
    for (int i = 0; i < 8; i++) {
        int t = tid + i * 256;
        if (t < T) attn[b * T + t] = le[i] * inv;
    }
}

#define TSPLIT 16
__global__ void k_context(const float* __restrict__ enc, const float* __restrict__ attn,
                          float* __restrict__ ctx) {
    int b = blockIdx.x, s = blockIdx.y;
    int e = threadIdx.x;
    int t0 = s * (T / TSPLIT), t1 = t0 + (T / TSPLIT);
    float acc = 0.f;
    for (int t = t0; t < t1; t++)
        acc += attn[b * T + t] * enc[((size_t)b * T + t) * E + e];
    atomicAdd(&ctx[b * E + e], acc);
}

// ---------------------------------------------------------------------------
extern "C" void kernel_launch(void* const* d_in, const int* in_sizes, int n_in,
                              void* d_out, int out_size) {
    const float* dec  = (const float*)d_in[0];
    const float* enc  = (const float*)d_in[1];
    const float* prev = (const float*)d_in[2];
    const int*   mask = (const int*)  d_in[3];
    const float* cw   = (const float*)d_in[4];
    const float* We   = (const float*)d_in[5];
    const float* Wd   = (const float*)d_in[6];
    const float* Wl   = (const float*)d_in[7];
    const float* vw   = (const float*)d_in[8];

    float* ctx  = (float*)d_out;
    float* attn = (float*)d_out + B * E;

    static int smem_set = 0;
    if (!smem_set) {
        cudaFuncSetAttribute(k_gemm_mma, cudaFuncAttributeMaxDynamicSharedMemorySize, SMEM_TOTAL);
        smem_set = 1;
    }

    k_init<<<(B * E + 255) / 256, 256>>>(ctx);
    k_prep_w<<<(A * KTOT + 255) / 256, 256>>>(We, Wl);
    k_dproj<<<B, 256>>>(dec, Wd);
    k_conv<<<dim3((T + CTV - 1) / CTV, B), 256>>>(prev, cw);
    k_gemm_mma<<<BT / 128, 256, SMEM_TOTAL>>>(enc, vw);
    k_softmax<<<B, 256>>>(mask, attn);
    k_context<<<dim3(B, TSPLIT), E>>>(enc, attn, ctx);
}